// round 8
// baseline (speedup 1.0000x reference)
#include <cuda_runtime.h>

#define T_LEN   750
#define CH      8
#define THREADS 96           // 94*8 = 752 >= 750; 3 warps
#define PAD_S   768          // staged length; max read idx = 744+15 = 759
#define NSLOT   64           // spread-atomic slots
#define SLOT_STRIDE 32       // 128B stride

// exp(-x/2) = exp2(-x * 0.5*log2(e))
#define NEG_HALF_LOG2E (-0.7213475204444817f)

__device__ float        g_slots[NSLOT * SLOT_STRIDE];   // zero-init at load
__device__ unsigned int g_count;                        // zero-init at load

__device__ __forceinline__ float ex2_approx(float x) {
    float r;
    asm("ex2.approx.ftz.f32 %0, %1;" : "=f"(r) : "f"(x));
    return r;
}

__global__ __launch_bounds__(THREADS, 10)
void ae_loss_kernel(const float* __restrict__ a0,
                    const float* __restrict__ a2,
                    float* __restrict__ out,
                    int B) {
    __shared__ __align__(16) float s0[PAD_S];
    __shared__ __align__(16) float s2[PAD_S];
    __shared__ float rw[THREADS / 32];
    __shared__ float rn[THREADS / 32];
    __shared__ bool  is_last;

    const int b   = blockIdx.x;
    const int tid = threadIdx.x;
    const float* __restrict__ g0 = a0 + (size_t)b * T_LEN;
    const float* __restrict__ g2 = a2 + (size_t)b * T_LEN;

    // Stage rows into shared (rows are 8B-aligned -> float2).
    {
        const float2* p0 = reinterpret_cast<const float2*>(g0);
        const float2* p2 = reinterpret_cast<const float2*>(g2);
        for (int k = tid; k < T_LEN / 2; k += THREADS) {   // 375 pairs
            float2 t0 = p0[k], t2 = p2[k];
            s0[2*k]   = t0.x; s0[2*k+1] = t0.y;
            s2[2*k]   = t2.x; s2[2*k+1] = t2.y;
        }
        if (tid < PAD_S - T_LEN) {          // finite filler; masked out below
            s0[T_LEN + tid] = g0[T_LEN - 1];
            s2[T_LEN + tid] = g2[T_LEN - 1];
        }
    }
    __syncthreads();

    const int i_base = tid * CH;
    float acc2a = 0.0f, acc2b = 0.0f;  // distance 1..2 / 3..4 (counted twice)
    float acc1  = 0.0f;                // distance 5..6        (counted once)
    float nsq   = 0.0f;                // sum (a0-a2)^2

    if (i_base < T_LEN) {
        // 16 consecutive floats cover outputs i_base..i_base+7 and partners +1..+6
        float v0[16], v2[16];
        const float4* p0 = reinterpret_cast<const float4*>(s0 + i_base);  // 16B aligned
        const float4* p2 = reinterpret_cast<const float4*>(s2 + i_base);
#pragma unroll
        for (int q = 0; q < 4; q++) {
            float4 t0 = p0[q], t2 = p2[q];
            v0[4*q+0]=t0.x; v0[4*q+1]=t0.y; v0[4*q+2]=t0.z; v0[4*q+3]=t0.w;
            v2[4*q+0]=t2.x; v2[4*q+1]=t2.y; v2[4*q+2]=t2.z; v2[4*q+3]=t2.w;
        }

        if (i_base + CH - 1 + 6 <= T_LEN - 1) {
            // Fast path: all outputs + partners in-range (tid <= 92)
#pragma unroll
            for (int c = 0; c < CH; c++) {
                const float x0 = v0[c], x2 = v2[c];
                const float d = x0 - x2;
                nsq = fmaf(d, d, nsq);
#pragma unroll
                for (int k = 1; k <= 6; k++) {
                    const float e = ex2_approx(fabsf(x0 - v0[c+k]) * NEG_HALF_LOG2E);
                    const float t = e * fabsf(x2 - v2[c+k]);
                    if      (k <= 2) acc2a += t;
                    else if (k <= 4) acc2b += t;
                    else             acc1  += t;
                }
            }
        } else {
            // Tail path (only thread 93 diverges here)
#pragma unroll
            for (int c = 0; c < CH; c++) {
                const int i = i_base + c;
                if (i < T_LEN) {
                    const float x0 = v0[c], x2 = v2[c];
                    const float d = x0 - x2;
                    nsq = fmaf(d, d, nsq);
#pragma unroll
                    for (int k = 1; k <= 6; k++) {
                        if (i + k < T_LEN) {
                            const float e = ex2_approx(fabsf(x0 - v0[c+k]) * NEG_HALF_LOG2E);
                            const float t = e * fabsf(x2 - v2[c+k]);
                            if      (k <= 2) acc2a += t;
                            else if (k <= 4) acc2b += t;
                            else             acc1  += t;
                        }
                    }
                }
            }
        }
    }

    float wsum = fmaf(2.0f, acc2a + acc2b, acc1);

    // Clamped-boundary extras (8 terms; replicates reference padding):
    //   left : u=1..5     -> (6-u)   * term(u, 0)
    //   right: u=746..748 -> (u-745) * term(u, 749)
    if (tid < 8) {
        int u, p; float mult;
        if (tid < 5) { u = tid + 1;   p = 0;         mult = (float)(5 - tid); }
        else         { u = 741 + tid; p = T_LEN - 1; mult = (float)(tid - 4); }
        const float e = ex2_approx(fabsf(s0[u] - s0[p]) * NEG_HALF_LOG2E);
        wsum = fmaf(mult * e, fabsf(s2[u] - s2[p]), wsum);
    }

    // Block reduction (3 warps)
#pragma unroll
    for (int o = 16; o > 0; o >>= 1) {
        wsum += __shfl_down_sync(0xFFFFFFFFu, wsum, o);
        nsq  += __shfl_down_sync(0xFFFFFFFFu, nsq,  o);
    }
    const int warp = tid >> 5, lane = tid & 31;
    if (lane == 0) { rw[warp] = wsum; rn[warp] = nsq; }
    __syncthreads();

    if (tid == 0) {
        float w = rw[0] + rw[1] + rw[2];
        float n = rn[0] + rn[1] + rn[2];
        atomicAdd(&g_slots[(b & (NSLOT - 1)) * SLOT_STRIDE], w + 0.1f * sqrtf(n));
        __threadfence();
        unsigned int prev = atomicAdd(&g_count, 1u);
        is_last = (prev == (unsigned int)(B - 1));
    }
    __syncthreads();

    // Last block: reduce slots, write result, reset state for next graph replay.
    if (is_last) {
        float v = 0.0f;
        if (tid < NSLOT)
            v = atomicAdd(&g_slots[tid * SLOT_STRIDE], 0.0f);  // L2-coherent read
#pragma unroll
        for (int o = 16; o > 0; o >>= 1)
            v += __shfl_down_sync(0xFFFFFFFFu, v, o);
        if (lane == 0 && warp < 2) rw[warp] = v;
        __syncthreads();
        if (tid == 0) {
            out[0] = rw[0] + rw[1];
            g_count = 0u;
        }
        __syncthreads();
        if (tid < NSLOT) g_slots[tid * SLOT_STRIDE] = 0.0f;
    }
}

extern "C" void kernel_launch(void* const* d_in, const int* in_sizes, int n_in,
                              void* d_out, int out_size) {
    const float* a0 = (const float*)d_in[0];
    const float* a2 = (const float*)d_in[1];
    float* out = (float*)d_out;

    const int B = in_sizes[0] / T_LEN;   // 4096

    ae_loss_kernel<<<B, THREADS>>>(a0, a2, out, B);
}

// round 9
// speedup vs baseline: 1.4227x; 1.4227x over previous
#include <cuda_runtime.h>

#define T_LEN   750
#define CH      4
#define THREADS 192          // 192*4 = 768 >= 750; 6 warps
#define NSLOT   64           // spread-atomic slots
#define SLOT_STRIDE 32       // 128B stride

// exp(-x/2) = exp2(-x * 0.5*log2(e))
#define NEG_HALF_LOG2E (-0.7213475204444817f)

__device__ float        g_slots[NSLOT * SLOT_STRIDE];   // zero-init at load
__device__ unsigned int g_count;                        // zero-init at load

__device__ __forceinline__ float ex2_approx(float x) {
    float r;
    asm("ex2.approx.ftz.f32 %0, %1;" : "=f"(r) : "f"(x));
    return r;
}

__global__ __launch_bounds__(THREADS)
void ae_loss_kernel(const float* __restrict__ a0,
                    const float* __restrict__ a2,
                    float* __restrict__ out,
                    int B) {
    __shared__ float rw[THREADS / 32];
    __shared__ float rn[THREADS / 32];
    __shared__ bool  is_last;

    const int b   = blockIdx.x;
    const int tid = threadIdx.x;
    const float* __restrict__ g0 = a0 + (size_t)b * T_LEN;
    const float* __restrict__ g2 = a2 + (size_t)b * T_LEN;

    const int i_base = tid * CH;
    float acc2a = 0.0f, acc2b = 0.0f;  // distance 1..2 / 3..4 (counted twice)
    float acc1  = 0.0f;                // distance 5..6        (counted once)
    float nsq   = 0.0f;                // sum (a0-a2)^2

    // Each thread needs padded[i_base .. i_base+9]: 4 outputs + partners +1..+6.
    // Rows start at even float offsets (750 even) and i_base is even, so
    // float2 loads are always aligned. Vector path valid iff i_base+9 <= 749,
    // which is exactly the fast-path (no clamp) condition.
    if (i_base < T_LEN) {
        float v0[10], v2[10];
        if (i_base + 9 <= T_LEN - 1) {
            const float2* p0 = reinterpret_cast<const float2*>(g0 + i_base);
            const float2* p2 = reinterpret_cast<const float2*>(g2 + i_base);
#pragma unroll
            for (int q = 0; q < 5; q++) {
                float2 t0 = p0[q], t2 = p2[q];
                v0[2*q] = t0.x; v0[2*q+1] = t0.y;
                v2[2*q] = t2.x; v2[2*q+1] = t2.y;
            }
            // Fast path: all 4 outputs and all partners in-range
#pragma unroll
            for (int c = 0; c < CH; c++) {
                const float x0 = v0[c], x2 = v2[c];
                const float d = x0 - x2;
                nsq = fmaf(d, d, nsq);
#pragma unroll
                for (int k = 1; k <= 6; k++) {
                    const float e = ex2_approx(fabsf(x0 - v0[c+k]) * NEG_HALF_LOG2E);
                    const float t = e * fabsf(x2 - v2[c+k]);
                    if      (k <= 2) acc2a += t;
                    else if (k <= 4) acc2b += t;
                    else             acc1  += t;
                }
            }
        } else {
            // Tail path (threads 186..191 only): clamped scalar loads + masked terms
#pragma unroll
            for (int m = 0; m < 10; m++) {
                int idx = i_base + m;
                idx = idx > T_LEN - 1 ? T_LEN - 1 : idx;
                v0[m] = g0[idx];
                v2[m] = g2[idx];
            }
#pragma unroll
            for (int c = 0; c < CH; c++) {
                const int i = i_base + c;
                if (i < T_LEN) {
                    const float x0 = v0[c], x2 = v2[c];
                    const float d = x0 - x2;
                    nsq = fmaf(d, d, nsq);
#pragma unroll
                    for (int k = 1; k <= 6; k++) {
                        if (i + k < T_LEN) {
                            const float e = ex2_approx(fabsf(x0 - v0[c+k]) * NEG_HALF_LOG2E);
                            const float t = e * fabsf(x2 - v2[c+k]);
                            if      (k <= 2) acc2a += t;
                            else if (k <= 4) acc2b += t;
                            else             acc1  += t;
                        }
                    }
                }
            }
        }
    }

    float wsum = fmaf(2.0f, acc2a + acc2b, acc1);

    // Clamped-boundary extras (8 terms; replicates reference padding):
    //   left : u=1..5     -> (6-u)   * term(u, 0)
    //   right: u=746..748 -> (u-745) * term(u, 749)
    if (tid < 8) {
        int u, p; float mult;
        if (tid < 5) { u = tid + 1;   p = 0;         mult = (float)(5 - tid); }
        else         { u = 741 + tid; p = T_LEN - 1; mult = (float)(tid - 4); }
        const float e = ex2_approx(fabsf(g0[u] - g0[p]) * NEG_HALF_LOG2E);
        wsum = fmaf(mult * e, fabsf(g2[u] - g2[p]), wsum);
    }

    // Block reduction (6 warps)
#pragma unroll
    for (int o = 16; o > 0; o >>= 1) {
        wsum += __shfl_down_sync(0xFFFFFFFFu, wsum, o);
        nsq  += __shfl_down_sync(0xFFFFFFFFu, nsq,  o);
    }
    const int warp = tid >> 5, lane = tid & 31;
    if (lane == 0) { rw[warp] = wsum; rn[warp] = nsq; }
    __syncthreads();

    if (tid == 0) {
        float w = rw[0], n = rn[0];
#pragma unroll
        for (int q = 1; q < THREADS / 32; q++) { w += rw[q]; n += rn[q]; }
        atomicAdd(&g_slots[(b & (NSLOT - 1)) * SLOT_STRIDE], w + 0.1f * sqrtf(n));
        __threadfence();
        unsigned int prev = atomicAdd(&g_count, 1u);
        is_last = (prev == (unsigned int)(B - 1));
    }
    __syncthreads();

    // Last block: reduce slots, write result, reset state for next graph replay.
    if (is_last) {
        float v = 0.0f;
        if (tid < NSLOT)
            v = atomicAdd(&g_slots[tid * SLOT_STRIDE], 0.0f);  // L2-coherent read
#pragma unroll
        for (int o = 16; o > 0; o >>= 1)
            v += __shfl_down_sync(0xFFFFFFFFu, v, o);
        if (lane == 0 && warp < 2) rw[warp] = v;
        __syncthreads();
        if (tid == 0) {
            out[0] = rw[0] + rw[1];
            g_count = 0u;
        }
        __syncthreads();
        if (tid < NSLOT) g_slots[tid * SLOT_STRIDE] = 0.0f;
    }
}

extern "C" void kernel_launch(void* const* d_in, const int* in_sizes, int n_in,
                              void* d_out, int out_size) {
    const float* a0 = (const float*)d_in[0];
    const float* a2 = (const float*)d_in[1];
    float* out = (float*)d_out;

    const int B = in_sizes[0] / T_LEN;   // 4096

    ae_loss_kernel<<<B, THREADS>>>(a0, a2, out, B);
}